// round 12
// baseline (speedup 1.0000x reference)
#include <cuda_runtime.h>
#include <cuda_bf16.h>
#include <cstdint>
#include <cstddef>

#define PB 256
#define PT 1024
#define PD 128
#define PH 256
#define BT (PB * PT)       // 262144 tokens
#define MTILES (BT / 128)  // 2048 (128-row tiles, MLP kernels)
#define GTILES (BT / 64)   // 4096 (64-row tiles, gate+scan kernel)

// ---------------- scratch (device globals; no cudaMalloc allowed) ----------
__device__ __nv_bfloat16 g_xb[(size_t)BT * 128];   // x in bf16
__device__ __nv_bfloat16 g_a[(size_t)BT * 128];    // MLP ping (padded)
__device__ __nv_bfloat16 g_b[(size_t)BT * 128];    // MLP pong
__device__ __nv_bfloat16 g_c[(size_t)BT * 64];     // layer-4 out (padded)
__device__ float g_pA[GTILES * 256];               // scan partials (fp32)
__device__ float g_pB[GTILES * 256];

// padded, transposed ([N, K] K-major) bf16 weights
__device__ __nv_bfloat16 g_WxT[256 * 128];
__device__ __nv_bfloat16 g_W1T[128 * 128];
__device__ __nv_bfloat16 g_W2T[128 * 128];
__device__ __nv_bfloat16 g_W3T[128 * 128];
__device__ __nv_bfloat16 g_W4T[64 * 128];
__device__ __nv_bfloat16 g_W5T[256 * 64];
__device__ float g_b1p[128], g_b2p[128], g_b3p[128], g_b4p[64];

__device__ __forceinline__ float sigf(float x) { return 1.f / (1.f + __expf(-x)); }

__device__ __forceinline__ uint32_t smem_u32(const void* p) {
    uint32_t a;
    asm("{ .reg .u64 t; cvta.to.shared.u64 t, %1; cvt.u32.u64 %0, t; }" : "=r"(a) : "l"(p));
    return a;
}
__device__ __forceinline__ void cp16(uint32_t dst, const void* src) {
    asm volatile("cp.async.ca.shared.global [%0], [%1], 16;" :: "r"(dst), "l"(src) : "memory");
}
__device__ __forceinline__ void cp_commit() {
    asm volatile("cp.async.commit_group;" ::: "memory");
}
template <int N>
__device__ __forceinline__ void cp_wait() {
    asm volatile("cp.async.wait_group %0;" :: "n"(N) : "memory");
}
__device__ __forceinline__ void mma16(float* c, const uint32_t* a, uint32_t b0, uint32_t b1) {
    asm volatile(
        "mma.sync.aligned.m16n8k16.row.col.f32.bf16.bf16.f32 "
        "{%0,%1,%2,%3}, {%4,%5,%6,%7}, {%8,%9}, {%0,%1,%2,%3};"
        : "+f"(c[0]), "+f"(c[1]), "+f"(c[2]), "+f"(c[3])
        : "r"(a[0]), "r"(a[1]), "r"(a[2]), "r"(a[3]), "r"(b0), "r"(b1));
}
__device__ __forceinline__ void ldsm4(uint32_t* r, uint32_t addr) {
    asm volatile("ldmatrix.sync.aligned.m8n8.x4.shared.b16 {%0,%1,%2,%3}, [%4];"
                 : "=r"(r[0]), "=r"(r[1]), "=r"(r[2]), "=r"(r[3]) : "r"(addr));
}

// ---------------- weight prep: transpose + pad + bf16 ----------------------
__global__ void prep_kernel(const float* __restrict__ Wx,
                            const float* __restrict__ W1, const float* __restrict__ b1,
                            const float* __restrict__ W2, const float* __restrict__ b2,
                            const float* __restrict__ W3, const float* __restrict__ b3,
                            const float* __restrict__ W4, const float* __restrict__ b4,
                            const float* __restrict__ W5)
{
    int t = blockIdx.x * blockDim.x + threadIdx.x;
    int S = gridDim.x * blockDim.x;
    for (int i = t; i < 256 * 128; i += S) { int n = i >> 7, k = i & 127; g_WxT[i] = __float2bfloat16(Wx[k * 256 + n]); }
    for (int i = t; i < 128 * 128; i += S) { int n = i >> 7, k = i & 127; g_W1T[i] = __float2bfloat16((n < 100) ? W1[k * 100 + n] : 0.f); }
    for (int i = t; i < 128 * 128; i += S) { int n = i >> 7, k = i & 127; g_W2T[i] = __float2bfloat16((n < 100 && k < 100) ? W2[k * 100 + n] : 0.f); }
    for (int i = t; i < 128 * 128; i += S) { int n = i >> 7, k = i & 127; g_W3T[i] = __float2bfloat16((n < 100 && k < 100) ? W3[k * 100 + n] : 0.f); }
    for (int i = t; i < 64 * 128;  i += S) { int n = i >> 7, k = i & 127; g_W4T[i] = __float2bfloat16((n < 50 && k < 100) ? W4[k * 50 + n] : 0.f); }
    for (int i = t; i < 256 * 64;  i += S) { int n = i >> 6, k = i & 63;  g_W5T[i] = __float2bfloat16((k < 50) ? W5[k * 256 + n] : 0.f); }
    for (int i = t; i < 128; i += S) {
        g_b1p[i] = (i < 100) ? b1[i] : 0.f;
        g_b2p[i] = (i < 100) ? b2[i] : 0.f;
        g_b3p[i] = (i < 100) ? b3[i] : 0.f;
    }
    for (int i = t; i < 64; i += S) g_b4p[i] = (i < 50) ? b4[i] : 0.f;
}

// ---------------- x -> bf16 -------------------------------------------------
__global__ void __launch_bounds__(256)
conv_x(const float* __restrict__ x, __nv_bfloat16* __restrict__ xb)
{
    size_t i = ((size_t)blockIdx.x * 256 + threadIdx.x) * 4;
    float4 v = *(const float4*)(x + i);
    __nv_bfloat162* o = (__nv_bfloat162*)(xb + i);
    o[0] = __floats2bfloat162_rn(v.x, v.y);
    o[1] = __floats2bfloat162_rn(v.z, v.w);
}

// ---------------- persistent bf16 GEMM (relu), ldmatrix fragments ----------
template <int K, int NFULL, int BN>
__global__ void __launch_bounds__(256, 2)
pgemm(const __nv_bfloat16* __restrict__ A, const __nv_bfloat16* __restrict__ Bw,
      const float* __restrict__ bias, __nv_bfloat16* __restrict__ C)
{
    constexpr int PITCH = K + 8;
    constexpr int WELEM = BN * PITCH;
    constexpr int ASTAGE = 128 * PITCH;
    constexpr int WN = BN / 2;
    constexpr int NT = WN / 8;
    extern __shared__ __nv_bfloat16 smb[];
    const uint32_t sbase = smem_u32(smb);

    const int tid = threadIdx.x;
    const int lane = tid & 31, wid = tid >> 5;
    const int gq = lane >> 2, tig = lane & 3;
    const int wm = wid & 3, wn = wid >> 2;
    const int colBase = blockIdx.x * BN;
    const int t0 = blockIdx.y, stride = gridDim.y;

    const int lrow = ((lane >> 3) & 1) * 8 + (lane & 7);
    const int lcolA = (lane >> 4) * 8;
    const uint32_t aOffL = (uint32_t)((wm * 32 + lrow) * PITCH + lcolA) * 2u;
    const uint32_t bBase = sbase + (uint32_t)((wn * WN + lrow) * PITCH + lcolA) * 2u;

    for (int id = tid; id < BN * (K / 8); id += 256) {
        int r = id / (K / 8), sg = (id % (K / 8)) * 8;
        cp16(sbase + (uint32_t)(r * PITCH + sg) * 2u, Bw + (size_t)(colBase + r) * K + sg);
    }
    cp_commit();

    auto loadA = [&](int tile, int buf) {
        if (tile < MTILES) {
            const size_t rb = (size_t)tile * 128;
            #pragma unroll
            for (int it = 0; it < (K / 8) * 128 / 256; it++) {
                int id = tid + it * 256;
                int r = id / (K / 8), sg = (id % (K / 8)) * 8;
                cp16(sbase + (uint32_t)(WELEM + buf * ASTAGE + r * PITCH + sg) * 2u,
                     A + (rb + r) * K + sg);
            }
        }
        cp_commit();
    };
    loadA(t0, 0);
    loadA(t0 + stride, 1);

    float bs[NT][2];
    #pragma unroll
    for (int nt = 0; nt < NT; nt++) {
        const int c0 = colBase + wn * WN + nt * 8 + 2 * tig;
        bs[nt][0] = __ldg(bias + c0);
        bs[nt][1] = __ldg(bias + c0 + 1);
    }

    for (int t = t0, it = 0; t < MTILES; t += stride, it++) {
        cp_wait<1>();
        __syncthreads();
        const uint32_t aBase = sbase + (uint32_t)(WELEM + (it & 1) * ASTAGE) * 2u + aOffL;

        float acc[2][NT][4];
        #pragma unroll
        for (int mt = 0; mt < 2; mt++)
            #pragma unroll
            for (int nt = 0; nt < NT; nt++)
                #pragma unroll
                for (int j = 0; j < 4; j++) acc[mt][nt][j] = 0.f;

        #pragma unroll
        for (int s = 0; s < K / 16; s++) {
            const uint32_t k2 = (uint32_t)(s * 16) * 2u;
            uint32_t af[2][4];
            ldsm4(af[0], aBase + k2);
            ldsm4(af[1], aBase + (uint32_t)(16 * PITCH) * 2u + k2);
            #pragma unroll
            for (int p = 0; p < NT / 2; p++) {
                uint32_t bf[4];
                ldsm4(bf, bBase + (uint32_t)(p * 16 * PITCH) * 2u + k2);
                mma16(acc[0][2 * p],     af[0], bf[0], bf[2]);
                mma16(acc[1][2 * p],     af[1], bf[0], bf[2]);
                mma16(acc[0][2 * p + 1], af[0], bf[1], bf[3]);
                mma16(acc[1][2 * p + 1], af[1], bf[1], bf[3]);
            }
        }
        __syncthreads();
        loadA(t + 2 * stride, it & 1);

        const size_t rowBase = (size_t)t * 128;
        #pragma unroll
        for (int mt = 0; mt < 2; mt++)
            #pragma unroll
            for (int nt = 0; nt < NT; nt++) {
                const int c0 = colBase + wn * WN + nt * 8 + 2 * tig;
                #pragma unroll
                for (int h = 0; h < 2; h++) {
                    const size_t r = rowBase + wm * 32 + mt * 16 + gq + h * 8;
                    float v0 = fmaxf(acc[mt][nt][2 * h + 0] + bs[nt][0], 0.f);
                    float v1 = fmaxf(acc[mt][nt][2 * h + 1] + bs[nt][1], 0.f);
                    *(__nv_bfloat162*)(C + r * NFULL + c0) = __floats2bfloat162_rn(v0, v1);
                }
            }
    }
}

// ---------------- fused gate GEMM + in-smem scan -----------------------------
// One CTA per 64-token tile (persistent): gate = sig(vc@W5+b5)*sig(xb@Wx+bx)
// computed full-width (256 cols) into SMEM, then the max-plus scan partial for
// this (batch, 64-timestep) chunk is computed in-SMEM. Gate never hits DRAM.
#define PXE 136
#define PVE 72
#define GPE 264
#define WXO 0                         // Wx: 256 x PXE = 34816 elems
#define W5O 34816                     // W5: 256 x PVE = 18432
#define XS0 53248                     // xb stage 0: 64 x PXE = 8704
#define XS1 61952
#define VS0 70656                     // vc stage 0: 64 x PVE = 4608
#define VS1 75264
#define GBO 79872                     // gate tile: 64 x GPE = 16896
#define EXO 96768                     // exchange: 512 floats = 1024 elems
#define GS_ELEMS 97792
#define GS_BYTES (GS_ELEMS * 2)       // 195584

__global__ void __launch_bounds__(512, 1)
pgatescan(const __nv_bfloat16* __restrict__ xb, const float* __restrict__ bx,
          const __nv_bfloat16* __restrict__ vc, const float* __restrict__ b5,
          const __nv_bfloat16* __restrict__ WxTg, const __nv_bfloat16* __restrict__ W5Tg,
          float* __restrict__ pA, float* __restrict__ pB)
{
    extern __shared__ __nv_bfloat16 smb[];
    const uint32_t sbase = smem_u32(smb);
    const int tid = threadIdx.x;
    const int lane = tid & 31, wid = tid >> 5;
    const int gq = lane >> 2, tig = lane & 3;
    const int wm = wid & 3, wn = wid >> 2;        // 4x4 warps; warp tile 16x64
    const int t0 = blockIdx.x, stride = gridDim.x;

    const int lrow = ((lane >> 3) & 1) * 8 + (lane & 7);
    const int lcol = (lane >> 4) * 8;
    const uint32_t aOffX = (uint32_t)((wm * 16 + lrow) * PXE + lcol) * 2u;
    const uint32_t aOffV = (uint32_t)((wm * 16 + lrow) * PVE + lcol) * 2u;
    const uint32_t bBaseX = sbase + (uint32_t)(WXO + (wn * 64 + lrow) * PXE + lcol) * 2u;
    const uint32_t bBaseV = sbase + (uint32_t)(W5O + (wn * 64 + lrow) * PVE + lcol) * 2u;

    // resident weights (one commit group)
    for (int id = tid; id < 256 * 16; id += 512) {
        int r = id >> 4, sg = (id & 15) * 8;
        cp16(sbase + (uint32_t)(WXO + r * PXE + sg) * 2u, WxTg + (size_t)r * 128 + sg);
    }
    for (int id = tid; id < 256 * 8; id += 512) {
        int r = id >> 3, sg = (id & 7) * 8;
        cp16(sbase + (uint32_t)(W5O + r * PVE + sg) * 2u, W5Tg + (size_t)r * 64 + sg);
    }
    cp_commit();

    auto load_stage = [&](int tile, int buf) {
        if (tile < GTILES) {
            const size_t rb = (size_t)tile * 64;
            const int xoff = buf ? XS1 : XS0;
            const int voff = buf ? VS1 : VS0;
            #pragma unroll
            for (int it = 0; it < 2; it++) {
                int id = tid + it * 512;
                int r = id >> 4, sg = (id & 15) * 8;
                cp16(sbase + (uint32_t)(xoff + r * PXE + sg) * 2u, xb + (rb + r) * 128 + sg);
            }
            {
                int r = tid >> 3, sg = (tid & 7) * 8;
                cp16(sbase + (uint32_t)(voff + r * PVE + sg) * 2u, vc + (rb + r) * 64 + sg);
            }
        }
        cp_commit();
    };
    load_stage(t0, 0);
    load_stage(t0 + stride, 1);

    const int si = tid & 255, sub = tid >> 8;
    float* exA = (float*)(smb + EXO);
    float* exB = exA + 256;

    for (int t = t0, it = 0; t < GTILES; t += stride, it++) {
        cp_wait<1>();
        __syncthreads();                      // stage ready; prev scan reads done
        const uint32_t xBase = sbase + (uint32_t)(it & 1 ? XS1 : XS0) * 2u + aOffX;
        const uint32_t vBase = sbase + (uint32_t)(it & 1 ? VS1 : VS0) * 2u + aOffV;

        float lin[8][4], fx[8][4];
        #pragma unroll
        for (int nt = 0; nt < 8; nt++)
            #pragma unroll
            for (int j = 0; j < 4; j++) { lin[nt][j] = 0.f; fx[nt][j] = 0.f; }

        // lin = Xs @ Wx (K=128)
        #pragma unroll
        for (int s = 0; s < 8; s++) {
            const uint32_t k2 = (uint32_t)(s * 16) * 2u;
            uint32_t af[4];
            ldsm4(af, xBase + k2);
            #pragma unroll
            for (int p = 0; p < 4; p++) {
                uint32_t bf[4];
                ldsm4(bf, bBaseX + (uint32_t)(p * 16 * PXE) * 2u + k2);
                mma16(lin[2 * p],     af, bf[0], bf[2]);
                mma16(lin[2 * p + 1], af, bf[1], bf[3]);
            }
        }
        // fx = Vs @ W5 (K=64)
        #pragma unroll
        for (int s = 0; s < 4; s++) {
            const uint32_t k2 = (uint32_t)(s * 16) * 2u;
            uint32_t af[4];
            ldsm4(af, vBase + k2);
            #pragma unroll
            for (int p = 0; p < 4; p++) {
                uint32_t bf[4];
                ldsm4(bf, bBaseV + (uint32_t)(p * 16 * PVE) * 2u + k2);
                mma16(fx[2 * p],     af, bf[0], bf[2]);
                mma16(fx[2 * p + 1], af, bf[1], bf[3]);
            }
        }

        // gate -> SMEM tile (bf16, same rounding as before)
        #pragma unroll
        for (int nt = 0; nt < 8; nt++) {
            const int c = wn * 64 + nt * 8 + 2 * tig;
            const float qx0 = __ldg(bx + c), qx1 = __ldg(bx + c + 1);
            const float q50 = __ldg(b5 + c), q51 = __ldg(b5 + c + 1);
            #pragma unroll
            for (int h = 0; h < 2; h++) {
                const int r = wm * 16 + gq + h * 8;
                float v0 = sigf(fx[nt][2 * h + 0] + q50) * sigf(lin[nt][2 * h + 0] + qx0);
                float v1 = sigf(fx[nt][2 * h + 1] + q51) * sigf(lin[nt][2 * h + 1] + qx1);
                *(__nv_bfloat162*)(smb + GBO + r * GPE + c) = __floats2bfloat162_rn(v0, v1);
            }
        }
        __syncthreads();                      // gate tile complete; stage consumed
        load_stage(t + 2 * stride, it & 1);   // prefetch overlaps scan

        // in-tile max-plus scan partial: col = (i + tglob + 1 + tloc) & 255
        {
            const int tg0 = (t & 15) * 64;
            float As = 0.f, Bs = -3.0e38f;
            int col = (si + tg0 + 1 + sub * 32) & 255;
            #pragma unroll 4
            for (int j = 0; j < 32; j++) {
                const int tl = sub * 32 + j;
                float val = __bfloat162float(smb[GBO + tl * GPE + col]);
                As += val;
                Bs = fmaxf(Bs + val, 0.f);
                col = (col + 1) & 255;
            }
            if (sub == 1) { exA[si] = As; exB[si] = Bs; }
            __syncthreads();
            if (sub == 0) {
                const float A1 = exA[si], B1 = exB[si];
                const size_t o = (size_t)t * 256 + si;
                pA[o] = As + A1;
                pB[o] = fmaxf(Bs + A1, B1);
            }
        }
    }
}

// ---------------- final combine + output head ------------------------------
__global__ void __launch_bounds__(256)
scan_fin(const float* __restrict__ pA, const float* __restrict__ pB,
         const float* __restrict__ Wo, const float* __restrict__ bo,
         float* __restrict__ out)
{
    const int b = blockIdx.x, i = threadIdx.x;
    float A = 0.f, B = -3.0e38f;
    #pragma unroll
    for (int c = 0; c < 16; c++) {
        const int o = (b * 16 + c) * 256 + i;
        float Ac = pA[o], Bc = pB[o];
        B = fmaxf(B + Ac, Bc);
        A += Ac;
    }
    const float v = fmaxf(A, B);
    out[PB + (size_t)b * 256 + i] = v;

    __shared__ float sh[256];
    sh[i] = v * Wo[i];
    __syncthreads();
    #pragma unroll
    for (int s = 128; s > 0; s >>= 1) {
        if (i < s) sh[i] += sh[i + s];
        __syncthreads();
    }
    if (i == 0) out[b] = 1.f / (1.f + __expf(-(sh[0] + bo[0])));
}

// ---------------- launch ---------------------------------------------------
extern "C" void kernel_launch(void* const* d_in, const int* in_sizes, int n_in,
                              void* d_out, int out_size)
{
    const float* x  = (const float*)d_in[0];
    const float* Wx = (const float*)d_in[1];
    const float* bx = (const float*)d_in[2];
    const float* W1 = (const float*)d_in[3];
    const float* b1 = (const float*)d_in[4];
    const float* W2 = (const float*)d_in[5];
    const float* b2 = (const float*)d_in[6];
    const float* W3 = (const float*)d_in[7];
    const float* b3 = (const float*)d_in[8];
    const float* W4 = (const float*)d_in[9];
    const float* b4 = (const float*)d_in[10];
    const float* W5 = (const float*)d_in[11];
    const float* b5 = (const float*)d_in[12];
    const float* Wo = (const float*)d_in[13];
    const float* bo = (const float*)d_in[14];
    float* out = (float*)d_out;

    void *p_xb, *p_a, *p_b, *p_c, *p_pA, *p_pB;
    void *p_WxT, *p_W1T, *p_W2T, *p_W3T, *p_W4T, *p_W5T;
    void *p_b1p, *p_b2p, *p_b3p, *p_b4p;
    cudaGetSymbolAddress(&p_xb, g_xb);
    cudaGetSymbolAddress(&p_a, g_a);
    cudaGetSymbolAddress(&p_b, g_b);
    cudaGetSymbolAddress(&p_c, g_c);
    cudaGetSymbolAddress(&p_pA, g_pA);
    cudaGetSymbolAddress(&p_pB, g_pB);
    cudaGetSymbolAddress(&p_WxT, g_WxT);
    cudaGetSymbolAddress(&p_W1T, g_W1T);
    cudaGetSymbolAddress(&p_W2T, g_W2T);
    cudaGetSymbolAddress(&p_W3T, g_W3T);
    cudaGetSymbolAddress(&p_W4T, g_W4T);
    cudaGetSymbolAddress(&p_W5T, g_W5T);
    cudaGetSymbolAddress(&p_b1p, g_b1p);
    cudaGetSymbolAddress(&p_b2p, g_b2p);
    cudaGetSymbolAddress(&p_b3p, g_b3p);
    cudaGetSymbolAddress(&p_b4p, g_b4p);
    __nv_bfloat16* xb = (__nv_bfloat16*)p_xb;
    __nv_bfloat16* va = (__nv_bfloat16*)p_a;
    __nv_bfloat16* vb = (__nv_bfloat16*)p_b;
    __nv_bfloat16* vc = (__nv_bfloat16*)p_c;

    constexpr int S_P128 = (128 * 136 + 2 * 128 * 136) * 2;   // 104448
    constexpr int S_P64  = (64 * 136 + 2 * 128 * 136) * 2;    // 87040
    cudaFuncSetAttribute(pgemm<128, 128, 128>, cudaFuncAttributeMaxDynamicSharedMemorySize, S_P128);
    cudaFuncSetAttribute(pgemm<128, 64, 64>,   cudaFuncAttributeMaxDynamicSharedMemorySize, S_P64);
    cudaFuncSetAttribute(pgatescan, cudaFuncAttributeMaxDynamicSharedMemorySize, GS_BYTES);

    prep_kernel<<<128, 256>>>(Wx, W1, b1, W2, b2, W3, b3, W4, b4, W5);
    conv_x<<<BT * 128 / (256 * 4), 256>>>(x, xb);

    // persistent MLP chain
    pgemm<128, 128, 128><<<dim3(1, 296), 256, S_P128>>>(xb, (const __nv_bfloat16*)p_W1T, (const float*)p_b1p, va);
    pgemm<128, 128, 128><<<dim3(1, 296), 256, S_P128>>>(va, (const __nv_bfloat16*)p_W2T, (const float*)p_b2p, vb);
    pgemm<128, 128, 128><<<dim3(1, 296), 256, S_P128>>>(vb, (const __nv_bfloat16*)p_W3T, (const float*)p_b3p, va);
    pgemm<128, 64, 64><<<dim3(1, 296), 256, S_P64>>>(va, (const __nv_bfloat16*)p_W4T, (const float*)p_b4p, vc);
    // fused gate GEMM + scan partials (gate never hits DRAM)
    pgatescan<<<148, 512, GS_BYTES>>>(xb, bx, vc, b5,
                                      (const __nv_bfloat16*)p_WxT, (const __nv_bfloat16*)p_W5T,
                                      (float*)p_pA, (float*)p_pB);
    // final combine + output head
    scan_fin<<<PB, 256>>>((const float*)p_pA, (const float*)p_pB, Wo, bo, out);
}